// round 14
// baseline (speedup 1.0000x reference)
#include <cuda_runtime.h>
#include <math.h>

#define BROWS 16
#define NSAMP 524288
#define LSEG  128
#define SSEG  4096              // segments per row
#define TSTR  160               // floats per map: [0]=t0, [32..159]=t1..t128 (640B)
#define PF    8                 // k_bound prefetch depth (compile-time slots)
#define CSH   1024.0f           // positive-domain shift (pre-applied in k_map)

__device__ float g_v[BROWS * NSAMP];                 // q * x_L
__device__ float g_t[(size_t)BROWS * SSEG * TSTR];   // pre-shifted map intercepts
__device__ float g_U[BROWS * SSEG];                  // exact segment seed states

__device__ __forceinline__ float sanitize(float v) {
    if (isnan(v)) v = 0.0f;
    if (v == 0.0f) v = 1e-10f;
    return v;
}

struct RowP { float aA, aR, q, thr, invr, knee, kq, gmk; };

__device__ __forceinline__ RowP row_params(const float* __restrict__ p, int b) {
    float p0 = sanitize(p[b * 6 + 0]);
    float p1 = sanitize(p[b * 6 + 1]);
    float p2 = sanitize(p[b * 6 + 2]);
    float p3 = sanitize(p[b * 6 + 3]);
    float p4 = sanitize(p[b * 6 + 4]);
    float p5 = sanitize(p[b * 6 + 5]);
    RowP r;
    r.thr = -p0 * 60.0f;
    float ratio = p1 * 10.0f;
    r.invr = 1.0f / ratio;
    float attack  = fmaxf(p2 / 10.0f, 1e-4f);
    float release = fmaxf(p3 * 3.0f, 0.005f);
    const float L9 = 2.1972245773362196f;
    r.aA = expf(-L9 / (44100.0f * attack));
    r.aR = expf(-L9 / (44100.0f * release));
    r.q = (r.aA <= r.aR) ? 1.0f : -1.0f;
    r.knee = p4 * 24.0f;
    r.kq = r.invr / (2.0f * r.knee);
    r.gmk = exp10f(p5 * 20.0f / 20.0f);
    return r;
}

// static gain curve -> v = q * x_L (fast log2 path)
__device__ __forceinline__ float v_of(float xi, const RowP& r) {
    float ax = fabsf(xi) + 1e-8f;
    float xg = fmaxf(6.02059991328f * __log2f(ax), -96.0f);   // 20*log10
    float d = xg - r.thr;
    float td = 2.0f * d;
    float h = (d + r.knee) * 0.5f;
    float xl_knee  = -(h * h) * r.kq;
    float xl_above = fmaf(-d, r.invr, d);
    float xl = (td < -r.knee) ? 0.0f : ((td > r.knee) ? xl_above : xl_knee);
    return r.q * xl;
}

// ---------------- Kernel 1: max-affine maps, 2 per warp, fused 2-step -------
// Map of segment s: u_{L(s+1)} = max_{j=0..L}( sig_j * u_{L s} + t_j ).
// Stores PRE-SHIFTED intercepts: t~_j = t_j + CSH*(1 - sig_j).
// Also writes g_v for its 256 samples (feeds k_apply).
__global__ void __launch_bounds__(256) k_map(const float* __restrict__ x,
                                             const float* __restrict__ p) {
    __shared__ float vbuf[8][260];
    __shared__ float csm[8][2][LSEG];
    int wid  = threadIdx.x >> 5;
    int lane = threadIdx.x & 31;
    int w = blockIdx.x * 8 + wid;          // 0 .. 32767
    int b  = w >> 11;                       // 2048 warps per row
    int s0 = (w & 2047) * 2;                // maps s0, s0+1 (map 4095 unused)
    RowP rp = row_params(p, b);
    float aA = rp.aA, aR = rp.aR;
    float aA2 = aA * aA, aR2 = aR * aR, aAR = aA * aR;

    const float* xb = x + (size_t)b * NSAMP;
    float* vout = g_v + (size_t)b * NSAMP;
    int base = s0 * LSEG;
    for (int i = lane; i < 260; i += 32) {
        int idx = base + i;
        idx = (idx < NSAMP) ? idx : (NSAMP - 1);
        vbuf[wid][i] = v_of(xb[idx], rp);
    }
    __syncwarp();
    for (int i = lane; i < 256; i += 32) vout[base + i] = vbuf[wid][i];
    for (int i = lane; i < LSEG; i += 32) {
        csm[wid][0][i] = vbuf[wid][i + 1]   - vbuf[wid][i + 2];
        csm[wid][1][i] = vbuf[wid][129 + i] - vbuf[wid][130 + i];
    }
    __syncwarp();

    const float NI = __int_as_float(0xff800000);   // -inf sentinel
    float ta0 = 0.0f, tb0 = 0.0f;                   // line j=0 of each map
    float a0 = NI, a1 = NI, a2 = NI, a3 = NI;       // map A: lines 4*lane+1..+4
    float b0 = NI, b1 = NI, b2 = NI, b3 = NI;       // map B

#pragma unroll 4
    for (int i = 0; i < LSEG; i += 2) {
        float ca1 = csm[wid][0][i], ca2 = csm[wid][0][i + 1];
        float cb1 = csm[wid][1][i], cb2 = csm[wid][1][i + 1];
        float da1 = fmaf(aA, ca1, ca2), da2 = fmaf(aR, ca1, ca2);
        float db1 = fmaf(aA, cb1, cb2), db2 = fmaf(aR, cb1, cb2);
        float dam = fmaxf(da1, da2),    dbm = fmaxf(db1, db2);
        float na1 = __shfl_up_sync(0xffffffffu, a3, 1);   // t_{4l}
        float na2 = __shfl_up_sync(0xffffffffu, a2, 1);   // t_{4l-1}
        float nb1 = __shfl_up_sync(0xffffffffu, b3, 1);
        float nb2 = __shfl_up_sync(0xffffffffu, b2, 1);
        if (lane == 0) { na1 = ta0; na2 = NI; nb1 = tb0; nb2 = NI; }
        a3 = fmaxf(fmaxf(fmaf(aA2, a3, da1), fmaf(aAR, a2, dam)), fmaf(aR2, a1, da2));
        b3 = fmaxf(fmaxf(fmaf(aA2, b3, db1), fmaf(aAR, b2, dbm)), fmaf(aR2, b1, db2));
        a2 = fmaxf(fmaxf(fmaf(aA2, a2, da1), fmaf(aAR, a1, dam)), fmaf(aR2, a0, da2));
        b2 = fmaxf(fmaxf(fmaf(aA2, b2, db1), fmaf(aAR, b1, dbm)), fmaf(aR2, b0, db2));
        a1 = fmaxf(fmaxf(fmaf(aA2, a1, da1), fmaf(aAR, a0, dam)), fmaf(aR2, na1, da2));
        b1 = fmaxf(fmaxf(fmaf(aA2, b1, db1), fmaf(aAR, b0, dbm)), fmaf(aR2, nb1, db2));
        a0 = fmaxf(fmaxf(fmaf(aA2, a0, da1), fmaf(aAR, na1, dam)), fmaf(aR2, na2, da2));
        b0 = fmaxf(fmaxf(fmaf(aA2, b0, db1), fmaf(aAR, nb1, dbm)), fmaf(aR2, nb2, db2));
        ta0 = fmaf(aA2, ta0, da1);
        tb0 = fmaf(aA2, tb0, db1);
    }

    // pre-shift: t~_j = t_j + CSH*(1 - sig_j), same sig formula as k_bound
    float la = __log2f(aA), lr = __log2f(aR);
    float cs0, cs1, cs2, cs3;
    {
        float j0 = (float)(4 * lane + 1);
        cs0 = CSH - CSH * exp2f(la * (128.0f - j0) + lr * j0);
        float j1 = j0 + 1.0f;
        cs1 = CSH - CSH * exp2f(la * (128.0f - j1) + lr * j1);
        float j2 = j0 + 2.0f;
        cs2 = CSH - CSH * exp2f(la * (128.0f - j2) + lr * j2);
        float j3 = j0 + 3.0f;
        cs3 = CSH - CSH * exp2f(la * (128.0f - j3) + lr * j3);
    }
    float cs00 = CSH - CSH * exp2f(la * 128.0f);

    float* TA = g_t + ((size_t)b * SSEG + s0) * TSTR;
    float* TB = TA + TSTR;
    if (lane == 0) { TA[0] = ta0 + cs00; TB[0] = tb0 + cs00; }
    reinterpret_cast<float4*>(TA + 32)[lane] =
        make_float4(a0 + cs0, a1 + cs1, a2 + cs2, a3 + cs3);
    reinterpret_cast<float4*>(TB + 32)[lane] =
        make_float4(b0 + cs0, b1 + cs1, b2 + cs2, b3 + cs3);
}

// ---------------- Kernel 2: chain boundaries (warp/row), pure-load prefetch -
__global__ void k_bound(const float* __restrict__ p) {
    int b = blockIdx.x;
    int lane = threadIdx.x;
    RowP rp = row_params(p, b);
    float la = __log2f(rp.aA), lr = __log2f(rp.aR);
    float sig[4];
#pragma unroll
    for (int i = 0; i < 4; i++) {
        float j = (float)(4 * lane + 1 + i);
        sig[i] = exp2f(la * (128.0f - j) + lr * j);
    }
    float sig0 = exp2f(la * 128.0f);             // uniform across lanes

    float u0 = -g_v[(size_t)b * NSAMP + 1];      // u_0 = -v[1]
    float ut = u0 + CSH;                          // shifted state (positive)
    if (lane == 0) g_U[b * SSEG + 0] = u0;

    const float* Tb = g_t + (size_t)b * SSEG * TSTR;
    float4 ta[PF];
    float t0a[PF];
#pragma unroll
    for (int k = 0; k < PF; k++) {
        const float* ts = Tb + (size_t)k * TSTR;
        ta[k]  = reinterpret_cast<const float4*>(ts + 32)[lane];
        t0a[k] = ts[0];
    }

    // SSEG iterations; last (s = 4095) computes a discarded value.
    for (int sb = 0; sb < SSEG; sb += PF) {
#pragma unroll
        for (int j = 0; j < PF; ++j) {           // compile-time slot -> regs
            int s = sb + j;
            float4 A = ta[j];
            float t0v = t0a[j];
            int sp = s + PF;
            if (sp < SSEG) {
                const float* ts = Tb + (size_t)sp * TSTR;
                ta[j]  = reinterpret_cast<const float4*>(ts + 32)[lane];
                t0a[j] = ts[0];
            }
            float m0 = fmaf(sig[0], ut, A.x);
            float m1 = fmaf(sig[1], ut, A.y);
            float m2 = fmaf(sig[2], ut, A.z);
            float m3 = fmaf(sig[3], ut, A.w);
            float m4 = fmaf(sig0, ut, t0v);      // line j=0, all lanes (uniform)
            float m = fmaxf(fmaxf(fmaxf(m0, m1), fmaxf(m2, m3)), m4);
            // all m > 0: raw bits order-isomorphic -> direct REDUX.UMAX
            unsigned rm = __reduce_max_sync(0xffffffffu, __float_as_uint(m));
            ut = __uint_as_float(rm);
            if (lane == 0 && (s + 1) < SSEG) g_U[b * SSEG + s + 1] = ut - CSH;
        }
    }
}

// ---------------- Kernel 3: per-segment rerun + fused output ---------------
#define STEPF(C) do { float c_ = (C); u = fmaxf(fmaf(aA, u, c_), fmaf(aR, u, c_)); } while (0)

__device__ __forceinline__ float emitv(float xi, float w, float q, float gmk) {
    float y = fmaxf(q * w, -96.0f);
    float val = xi * exp2f(-0.166096404744368f * y) * gmk;   // 10^(-y/20)
    return isfinite(val) ? val : 0.0f;
}

__global__ void __launch_bounds__(256) k_apply(const float* __restrict__ x,
                                               const float* __restrict__ p,
                                               float* __restrict__ out) {
    int tid = blockIdx.x * blockDim.x + threadIdx.x;   // 65536 threads
    int b = tid >> 12;
    int s = tid & (SSEG - 1);
    RowP r = row_params(p, b);
    float aA = r.aA, aR = r.aR, q = r.q, gmk = r.gmk;
    float u = g_U[(b << 12) + s];
    bool last = (s == SSEG - 1);

    const float4* V4 = reinterpret_cast<const float4*>(g_v) + (size_t)b * (NSAMP / 4) + s * (LSEG / 4);
    const float4* X4 = reinterpret_cast<const float4*>(x) + (size_t)b * (NSAMP / 4) + s * (LSEG / 4);
    float4* O4 = reinterpret_cast<float4*>(out) + (size_t)b * (NSAMP / 4) + s * (LSEG / 4);

    float4 vc = V4[0];
#pragma unroll 4
    for (int g = 0; g < LSEG / 4; ++g) {
        float4 vn;
        if (last && g == (LSEG / 4 - 1)) {
            vn = make_float4(0.0f, 0.0f, 0.0f, 0.0f);   // v_N = 0 convention
        } else {
            vn = V4[g + 1];
        }
        float4 xv = X4[g];
        float4 o;
        o.x = emitv(xv.x, u + vc.y, q, gmk); STEPF(vc.y - vc.z);
        o.y = emitv(xv.y, u + vc.z, q, gmk); STEPF(vc.z - vc.w);
        o.z = emitv(xv.z, u + vc.w, q, gmk); STEPF(vc.w - vn.x);
        o.w = emitv(xv.w, u + vn.x, q, gmk); STEPF(vn.x - vn.y);
        O4[g] = o;
        vc = vn;
    }
}

extern "C" void kernel_launch(void* const* d_in, const int* in_sizes, int n_in,
                              void* d_out, int out_size) {
    const float* x = (const float*)d_in[0];      // [16, 524288] f32
    const float* p = (const float*)d_in[1];      // [16, 6] f32
    float* out = (float*)d_out;

    k_map<<<4096, 256>>>(x, p);                  // 8 warps/block, 2 maps/warp
    k_bound<<<BROWS, 32>>>(p);
    k_apply<<<(BROWS * SSEG) / 256, 256>>>(x, p, out);
}

// round 15
// speedup vs baseline: 1.0184x; 1.0184x over previous
#include <cuda_runtime.h>
#include <math.h>

#define BROWS 16
#define NSAMP 524288
#define LSEG  128
#define SSEG  4096              // segments per row
#define TSTR  160               // floats per map: [0]=t0, [32..159]=t1..t128 (640B)
#define PF    8                 // k_bound prefetch depth (compile-time slots)
#define CSH   1024.0f           // positive-domain shift (pre-applied in k_map)

__device__ float g_v[BROWS * NSAMP];                 // q * x_L
__device__ float g_t[(size_t)BROWS * SSEG * TSTR];   // pre-shifted map intercepts
__device__ float g_U[BROWS * SSEG];                  // exact segment seed states

__device__ __forceinline__ float sanitize(float v) {
    if (isnan(v)) v = 0.0f;
    if (v == 0.0f) v = 1e-10f;
    return v;
}

struct RowP { float aA, aR, q, thr, invr, knee, kq, gmk; };

__device__ __forceinline__ RowP row_params(const float* __restrict__ p, int b) {
    float p0 = sanitize(p[b * 6 + 0]);
    float p1 = sanitize(p[b * 6 + 1]);
    float p2 = sanitize(p[b * 6 + 2]);
    float p3 = sanitize(p[b * 6 + 3]);
    float p4 = sanitize(p[b * 6 + 4]);
    float p5 = sanitize(p[b * 6 + 5]);
    RowP r;
    r.thr = -p0 * 60.0f;
    float ratio = p1 * 10.0f;
    r.invr = 1.0f / ratio;
    float attack  = fmaxf(p2 / 10.0f, 1e-4f);
    float release = fmaxf(p3 * 3.0f, 0.005f);
    const float L9 = 2.1972245773362196f;
    r.aA = expf(-L9 / (44100.0f * attack));
    r.aR = expf(-L9 / (44100.0f * release));
    r.q = (r.aA <= r.aR) ? 1.0f : -1.0f;
    r.knee = p4 * 24.0f;
    r.kq = r.invr / (2.0f * r.knee);
    r.gmk = exp10f(p5 * 20.0f / 20.0f);
    return r;
}

// static gain curve -> v = q * x_L (fast log2 path)
__device__ __forceinline__ float v_of(float xi, const RowP& r) {
    float ax = fabsf(xi) + 1e-8f;
    float xg = fmaxf(6.02059991328f * __log2f(ax), -96.0f);   // 20*log10
    float d = xg - r.thr;
    float td = 2.0f * d;
    float h = (d + r.knee) * 0.5f;
    float xl_knee  = -(h * h) * r.kq;
    float xl_above = fmaf(-d, r.invr, d);
    float xl = (td < -r.knee) ? 0.0f : ((td > r.knee) ? xl_above : xl_knee);
    return r.q * xl;
}

// ---------------- Kernel 1: max-affine maps, 2 per warp, fused 2-step -------
// Map of segment s: u_{L(s+1)} = max_{j=0..L}( sig_j * u_{L s} + t_j ).
// Stores PRE-SHIFTED intercepts: t~_j = t_j + CSH*(1 - sig_j).
// Also writes g_v for its 256 samples (feeds k_apply).
__global__ void __launch_bounds__(256) k_map(const float* __restrict__ x,
                                             const float* __restrict__ p) {
    __shared__ float vbuf[8][260];
    __shared__ float csm[8][2][LSEG];
    int wid  = threadIdx.x >> 5;
    int lane = threadIdx.x & 31;
    int w = blockIdx.x * 8 + wid;          // 0 .. 32767
    int b  = w >> 11;                       // 2048 warps per row
    int s0 = (w & 2047) * 2;                // maps s0, s0+1 (map 4095 unused)
    RowP rp = row_params(p, b);
    float aA = rp.aA, aR = rp.aR;
    float aA2 = aA * aA, aR2 = aR * aR, aAR = aA * aR;

    const float* xb = x + (size_t)b * NSAMP;
    float* vout = g_v + (size_t)b * NSAMP;
    int base = s0 * LSEG;
    for (int i = lane; i < 260; i += 32) {
        int idx = base + i;
        idx = (idx < NSAMP) ? idx : (NSAMP - 1);
        vbuf[wid][i] = v_of(xb[idx], rp);
    }
    __syncwarp();
    for (int i = lane; i < 256; i += 32) vout[base + i] = vbuf[wid][i];
    for (int i = lane; i < LSEG; i += 32) {
        csm[wid][0][i] = vbuf[wid][i + 1]   - vbuf[wid][i + 2];
        csm[wid][1][i] = vbuf[wid][129 + i] - vbuf[wid][130 + i];
    }
    __syncwarp();

    const float NI = __int_as_float(0xff800000);   // -inf sentinel
    float ta0 = 0.0f, tb0 = 0.0f;                   // line j=0 of each map
    float a0 = NI, a1 = NI, a2 = NI, a3 = NI;       // map A: lines 4*lane+1..+4
    float b0 = NI, b1 = NI, b2 = NI, b3 = NI;       // map B

#pragma unroll 4
    for (int i = 0; i < LSEG; i += 2) {
        float ca1 = csm[wid][0][i], ca2 = csm[wid][0][i + 1];
        float cb1 = csm[wid][1][i], cb2 = csm[wid][1][i + 1];
        float da1 = fmaf(aA, ca1, ca2), da2 = fmaf(aR, ca1, ca2);
        float db1 = fmaf(aA, cb1, cb2), db2 = fmaf(aR, cb1, cb2);
        float dam = fmaxf(da1, da2),    dbm = fmaxf(db1, db2);
        float na1 = __shfl_up_sync(0xffffffffu, a3, 1);   // t_{4l}
        float na2 = __shfl_up_sync(0xffffffffu, a2, 1);   // t_{4l-1}
        float nb1 = __shfl_up_sync(0xffffffffu, b3, 1);
        float nb2 = __shfl_up_sync(0xffffffffu, b2, 1);
        if (lane == 0) { na1 = ta0; na2 = NI; nb1 = tb0; nb2 = NI; }
        a3 = fmaxf(fmaxf(fmaf(aA2, a3, da1), fmaf(aAR, a2, dam)), fmaf(aR2, a1, da2));
        b3 = fmaxf(fmaxf(fmaf(aA2, b3, db1), fmaf(aAR, b2, dbm)), fmaf(aR2, b1, db2));
        a2 = fmaxf(fmaxf(fmaf(aA2, a2, da1), fmaf(aAR, a1, dam)), fmaf(aR2, a0, da2));
        b2 = fmaxf(fmaxf(fmaf(aA2, b2, db1), fmaf(aAR, b1, dbm)), fmaf(aR2, b0, db2));
        a1 = fmaxf(fmaxf(fmaf(aA2, a1, da1), fmaf(aAR, a0, dam)), fmaf(aR2, na1, da2));
        b1 = fmaxf(fmaxf(fmaf(aA2, b1, db1), fmaf(aAR, b0, dbm)), fmaf(aR2, nb1, db2));
        a0 = fmaxf(fmaxf(fmaf(aA2, a0, da1), fmaf(aAR, na1, dam)), fmaf(aR2, na2, da2));
        b0 = fmaxf(fmaxf(fmaf(aA2, b0, db1), fmaf(aAR, nb1, dbm)), fmaf(aR2, nb2, db2));
        ta0 = fmaf(aA2, ta0, da1);
        tb0 = fmaf(aA2, tb0, db1);
    }

    // pre-shift: t~_j = t_j + CSH*(1 - sig_j), same sig formula as k_bound
    float la = __log2f(aA), lr = __log2f(aR);
    float cs0, cs1, cs2, cs3;
    {
        float j0 = (float)(4 * lane + 1);
        cs0 = CSH - CSH * exp2f(la * (128.0f - j0) + lr * j0);
        float j1 = j0 + 1.0f;
        cs1 = CSH - CSH * exp2f(la * (128.0f - j1) + lr * j1);
        float j2 = j0 + 2.0f;
        cs2 = CSH - CSH * exp2f(la * (128.0f - j2) + lr * j2);
        float j3 = j0 + 3.0f;
        cs3 = CSH - CSH * exp2f(la * (128.0f - j3) + lr * j3);
    }
    float cs00 = CSH - CSH * exp2f(la * 128.0f);

    float* TA = g_t + ((size_t)b * SSEG + s0) * TSTR;
    float* TB = TA + TSTR;
    if (lane == 0) { TA[0] = ta0 + cs00; TB[0] = tb0 + cs00; }
    reinterpret_cast<float4*>(TA + 32)[lane] =
        make_float4(a0 + cs0, a1 + cs1, a2 + cs2, a3 + cs3);
    reinterpret_cast<float4*>(TB + 32)[lane] =
        make_float4(b0 + cs0, b1 + cs1, b2 + cs2, b3 + cs3);
}

// ---------------- Kernel 2: chain boundaries (warp/row), pure-load prefetch -
__global__ void k_bound(const float* __restrict__ p) {
    int b = blockIdx.x;
    int lane = threadIdx.x;
    RowP rp = row_params(p, b);
    float la = __log2f(rp.aA), lr = __log2f(rp.aR);
    float sig[4];
#pragma unroll
    for (int i = 0; i < 4; i++) {
        float j = (float)(4 * lane + 1 + i);
        sig[i] = exp2f(la * (128.0f - j) + lr * j);
    }
    float sig0 = exp2f(la * 128.0f);             // uniform across lanes

    float u0 = -g_v[(size_t)b * NSAMP + 1];      // u_0 = -v[1]
    float ut = u0 + CSH;                          // shifted state (positive)
    if (lane == 0) g_U[b * SSEG + 0] = u0;

    const float* Tb = g_t + (size_t)b * SSEG * TSTR;
    float4 ta[PF];
    float t0a[PF];
#pragma unroll
    for (int k = 0; k < PF; k++) {
        const float* ts = Tb + (size_t)k * TSTR;
        ta[k]  = reinterpret_cast<const float4*>(ts + 32)[lane];
        t0a[k] = ts[0];
    }

    // SSEG iterations; last (s = 4095) computes a discarded value.
    for (int sb = 0; sb < SSEG; sb += PF) {
#pragma unroll
        for (int j = 0; j < PF; ++j) {           // compile-time slot -> regs
            int s = sb + j;
            float4 A = ta[j];
            float t0v = t0a[j];
            int sp = s + PF;
            if (sp < SSEG) {
                const float* ts = Tb + (size_t)sp * TSTR;
                ta[j]  = reinterpret_cast<const float4*>(ts + 32)[lane];
                t0a[j] = ts[0];
            }
            float m0 = fmaf(sig[0], ut, A.x);
            float m1 = fmaf(sig[1], ut, A.y);
            float m2 = fmaf(sig[2], ut, A.z);
            float m3 = fmaf(sig[3], ut, A.w);
            float m4 = fmaf(sig0, ut, t0v);      // line j=0, all lanes (uniform)
            float m = fmaxf(fmaxf(fmaxf(m0, m1), fmaxf(m2, m3)), m4);
            // all m > 0: raw bits order-isomorphic -> direct REDUX.UMAX
            unsigned rm = __reduce_max_sync(0xffffffffu, __float_as_uint(m));
            ut = __uint_as_float(rm);
            if (lane == 0 && (s + 1) < SSEG) g_U[b * SSEG + s + 1] = ut - CSH;
        }
    }
}

// ---------------- Kernel 3: per-segment rerun + fused output ---------------
#define STEPF(C) do { float c_ = (C); u = fmaxf(fmaf(aA, u, c_), fmaf(aR, u, c_)); } while (0)

__device__ __forceinline__ float emitv(float xi, float w, float q, float gmk) {
    float y = fmaxf(q * w, -96.0f);
    float val = xi * exp2f(-0.166096404744368f * y) * gmk;   // 10^(-y/20)
    return isfinite(val) ? val : 0.0f;
}

__global__ void __launch_bounds__(256) k_apply(const float* __restrict__ x,
                                               const float* __restrict__ p,
                                               float* __restrict__ out) {
    int tid = blockIdx.x * blockDim.x + threadIdx.x;   // 65536 threads
    int b = tid >> 12;
    int s = tid & (SSEG - 1);
    RowP r = row_params(p, b);
    float aA = r.aA, aR = r.aR, q = r.q, gmk = r.gmk;
    float u = g_U[(b << 12) + s];
    bool last = (s == SSEG - 1);

    const float4* V4 = reinterpret_cast<const float4*>(g_v) + (size_t)b * (NSAMP / 4) + s * (LSEG / 4);
    const float4* X4 = reinterpret_cast<const float4*>(x) + (size_t)b * (NSAMP / 4) + s * (LSEG / 4);
    float4* O4 = reinterpret_cast<float4*>(out) + (size_t)b * (NSAMP / 4) + s * (LSEG / 4);

    float4 vc = V4[0];
#pragma unroll 4
    for (int g = 0; g < LSEG / 4; ++g) {
        float4 vn;
        if (last && g == (LSEG / 4 - 1)) {
            vn = make_float4(0.0f, 0.0f, 0.0f, 0.0f);   // v_N = 0 convention
        } else {
            vn = V4[g + 1];
        }
        float4 xv = X4[g];
        float4 o;
        o.x = emitv(xv.x, u + vc.y, q, gmk); STEPF(vc.y - vc.z);
        o.y = emitv(xv.y, u + vc.z, q, gmk); STEPF(vc.z - vc.w);
        o.z = emitv(xv.z, u + vc.w, q, gmk); STEPF(vc.w - vn.x);
        o.w = emitv(xv.w, u + vn.x, q, gmk); STEPF(vn.x - vn.y);
        O4[g] = o;
        vc = vn;
    }
}

extern "C" void kernel_launch(void* const* d_in, const int* in_sizes, int n_in,
                              void* d_out, int out_size) {
    const float* x = (const float*)d_in[0];      // [16, 524288] f32
    const float* p = (const float*)d_in[1];      // [16, 6] f32
    float* out = (float*)d_out;

    k_map<<<4096, 256>>>(x, p);                  // 8 warps/block, 2 maps/warp
    k_bound<<<BROWS, 32>>>(p);
    k_apply<<<(BROWS * SSEG) / 256, 256>>>(x, p, out);
}